// round 16
// baseline (speedup 1.0000x reference)
#include <cuda_runtime.h>
#include <cuda_bf16.h>

// S4D layer: B=8, H=128, N=64, L=8192.
// y[b,h,l] = Re( sum_n g_n * s_n[l] ) + D[h]*x[b,h,l]
// s_n[l] = w_n * s_n[l-1] + x[b,h,l],  s_n[-1] = 0
// w_n = exp(dt*A_n), g_n = Cc_n * (exp(dt*A_n)-1)/A_n   (complex, per (h,n))
//
// One warp per (b,h) row; 2 complex states per lane packed into f32x2 vectors;
// packed FFMA2 (fma.rn.f32x2) for the recurrence; per-32-step register-buffered
// partials reduced across lanes by a log2 shfl transpose-fold.

#define HH 128
#define BB 8
#define LL 8192
#define NN 64

typedef unsigned long long u64;

__device__ __forceinline__ u64 pk2(float lo, float hi) {
    u64 r; asm("mov.b64 %0, {%1, %2};" : "=l"(r) : "f"(lo), "f"(hi)); return r;
}
__device__ __forceinline__ void upk2(u64 v, float& lo, float& hi) {
    asm("mov.b64 {%0, %1}, %2;" : "=f"(lo), "=f"(hi) : "l"(v));
}
__device__ __forceinline__ u64 fma2(u64 a, u64 b, u64 c) {
    u64 d; asm("fma.rn.f32x2 %0, %1, %2, %3;" : "=l"(d) : "l"(a), "l"(b), "l"(c)); return d;
}
__device__ __forceinline__ u64 mul2(u64 a, u64 b) {
    u64 d; asm("mul.rn.f32x2 %0, %1, %2;" : "=l"(d) : "l"(a), "l"(b)); return d;
}

__global__ void __launch_bounds__(32) s4d_scan_kernel(
    const float* __restrict__ x,      // (B,H,L)
    const float* __restrict__ Are,    // (H,N,1)
    const float* __restrict__ Aim,    // (H,N,1)
    const float* __restrict__ Cm,     // (H,N,2)
    const float* __restrict__ Dv,     // (1,H,1)
    const float* __restrict__ logdt,  // (H,1,1)
    float* __restrict__ out)          // (B,H,L)
{
    const int g    = blockIdx.x;        // g = b*H + h
    const int h    = g & (HH - 1);
    const int lane = threadIdx.x;

    // ---- per-mode parameter setup (double precision: errors in w compound
    //      multiplicatively over the 8192-step horizon, so w must be accurate
    //      to fp32 quantization, not float-transcendental accuracy) ----
    const double dt = exp((double)logdt[h]);
    float wrf[2], wif[2], grf[2], gif[2];
#pragma unroll
    for (int k = 0; k < 2; ++k) {
        const int idx = h * NN + lane + 32 * k;
        const double ar = fmin((double)Are[idx], -1e-4);
        const double ai = (double)Aim[idx];
        const double er = exp(dt * ar);
        double si, co; sincos(dt * ai, &si, &co);
        const double wr = er * co, wi = er * si;
        // cons = (w - 1)/A  (complex division)
        const double den = ar * ar + ai * ai;
        const double cr  = ((wr - 1.0) * ar + wi * ai) / den;
        const double ci  = (wi * ar - (wr - 1.0) * ai) / den;
        // g = Cc * cons, Cc = C[...,0] + i*C[...,1]
        const double Cre = (double)Cm[idx * 2 + 0];
        const double Cim = (double)Cm[idx * 2 + 1];
        grf[k] = (float)(Cre * cr - Cim * ci);
        gif[k] = (float)(Cre * ci + Cim * cr);
        wrf[k] = (float)wr;
        wif[k] = (float)wi;
    }
    const u64 wrv  = pk2(wrf[0], wrf[1]);
    const u64 wiv  = pk2(wif[0], wif[1]);
    const u64 mwiv = pk2(-wif[0], -wif[1]);
    const u64 grv  = pk2(grf[0], grf[1]);
    const u64 mgiv = pk2(-gif[0], -gif[1]);
    const float Dh = Dv[h];

    u64 zr = pk2(0.f, 0.f);   // (Re s_n0, Re s_n1)
    u64 zi = pk2(0.f, 0.f);   // (Im s_n0, Im s_n1)

    const float* xrow = x   + (size_t)g * LL;
    float*       orow = out + (size_t)g * LL;

    float xnext = __ldg(xrow + lane);

    for (int l0 = 0; l0 < LL; l0 += 32) {
        const float xcur = xnext;
        if (l0 + 32 < LL) xnext = __ldg(xrow + l0 + 32 + lane);

        float part[32];
#pragma unroll
        for (int t = 0; t < 32; ++t) {
            const float xb = __shfl_sync(0xffffffffu, xcur, t);
            const u64 xp = pk2(xb, xb);
            // complex state update: z = w*z + x   (per packed pair of modes)
            const u64 t2  = mul2(wiv, zr);        // wi*zr_old
            u64       nzr = fma2(wrv, zr, xp);    // wr*zr_old + x
            nzr           = fma2(mwiv, zi, nzr);  // - wi*zi_old
            zi            = fma2(wrv, zi, t2);    // wr*zi_old + wi*zr_old
            zr            = nzr;
            // per-step output partial: Re(g * z) summed over this lane's 2 modes
            u64 pd = mul2(grv, zr);               // gr*zr
            pd     = fma2(mgiv, zi, pd);          // - gi*zi
            float plo, phi; upk2(pd, plo, phi);
            part[t] = plo + phi;
        }

        // ---- cross-lane transpose-fold: lane t ends with sum_lanes part[t] ----
#pragma unroll
        for (int o = 16; o >= 1; o >>= 1) {
            const bool hiHalf = (lane & o) != 0;
            float tmp[16];
#pragma unroll
            for (int t = 0; t < o; ++t) {
                const float a  = part[t];
                const float bq = part[t + o];
                const float send = hiHalf ? a : bq;
                const float recv = __shfl_xor_sync(0xffffffffu, send, o);
                tmp[t] = (hiHalf ? bq : a) + recv;
            }
#pragma unroll
            for (int t = 0; t < o; ++t) part[t] = tmp[t];
        }

        orow[l0 + lane] = fmaf(Dh, xcur, part[0]);
    }
}

extern "C" void kernel_launch(void* const* d_in, const int* in_sizes, int n_in,
                              void* d_out, int out_size)
{
    const float* x     = (const float*)d_in[0];
    const float* Are   = (const float*)d_in[1];
    const float* Aim   = (const float*)d_in[2];
    const float* Cm    = (const float*)d_in[3];
    const float* Dv    = (const float*)d_in[4];
    const float* logdt = (const float*)d_in[5];
    float* out = (float*)d_out;

    s4d_scan_kernel<<<BB * HH, 32>>>(x, Are, Aim, Cm, Dv, logdt, out);
}